// round 7
// baseline (speedup 1.0000x reference)
#include <cuda_runtime.h>
#include <math.h>

#define BB   4
#define SS   512
#define HH   256
#define VV   32000
#define MM   (BB*SS)     // 2048

// ---------------- device scratch (no allocation anywhere) ----------------
__device__ float g_embT[HH * MM];              // [k][bt]                2 MB
__device__ float g_xp[(size_t)MM * 768];       // [bt][row]              6 MB
__device__ float g_hsR[(size_t)MM * HH];       // [bt][perm(k)] rounded  2 MB
__device__ float g_WoutR[(size_t)VV * HH];     // [n][perm(k)] rounded  33 MB

// RNA round fp32 -> tf32 bit pattern (round-to-nearest, ties away)
__device__ __forceinline__ float rna_tf32(float v) {
    unsigned b = __float_as_uint(v);
    b = (b + 0x1000u) & 0xFFFFE000u;
    return __uint_as_float(b);
}
// permute k within 16-chunks: value at orig k goes to pos (k&~15) | ((k&3)<<2) | ((k>>2)&3)
__device__ __forceinline__ int permk(int k) {
    return (k & ~15) | ((k & 3) << 2) | ((k >> 2) & 3);
}

// ---------------- kernel A: gather emb -> transposed ----------------------
__global__ void gather_kernel(const int* __restrict__ x,
                              const float* __restrict__ emb)
{
    const int bt  = blockIdx.x;
    const int tid = threadIdx.x;             // 0..63
    const int tok = x[bt];
    const float4 v = *(const float4*)(emb + (size_t)tok * HH + tid * 4);
    const int k = tid * 4;
    g_embT[(k + 0) * MM + bt] = v.x;
    g_embT[(k + 1) * MM + bt] = v.y;
    g_embT[(k + 2) * MM + bt] = v.z;
    g_embT[(k + 3) * MM + bt] = v.w;
}

// ---------------- kernel B: xp = emb @ W_ih^T + b_ih ----------------------
__global__ void __launch_bounds__(256) inproj_kernel(
    const float* __restrict__ W_ih, const float* __restrict__ b_ih)
{
    __shared__ float sW[16 * 256];
    const int r0 = blockIdx.y * 16;
    const int bt = blockIdx.x * 256 + threadIdx.x;
    for (int i = threadIdx.x; i < 16 * 256; i += 256)
        sW[i] = W_ih[(size_t)r0 * 256 + i];
    __syncthreads();

    float acc[16];
#pragma unroll
    for (int ri = 0; ri < 16; ri++) acc[ri] = 0.f;

#pragma unroll 4
    for (int k = 0; k < HH; k++) {
        const float e = g_embT[k * MM + bt];
#pragma unroll
        for (int ri = 0; ri < 16; ri++)
            acc[ri] += e * sW[ri * 256 + k];
    }
    float* o = g_xp + (size_t)bt * 768 + r0;
#pragma unroll
    for (int ri = 0; ri < 16; ri++)
        o[ri] = acc[ri] + b_ih[r0 + ri];
}

// ---------------- kernel B2: round + permute W_out -------------------------
__global__ void __launch_bounds__(256) roundw_kernel(const float* __restrict__ Wout)
{
    const int n = blockIdx.x;
    const int k = threadIdx.x;
    g_WoutR[(size_t)n * HH + permk(k)] = rna_tf32(Wout[(size_t)n * HH + k]);
}

// ---------------- kernel C: GRU recurrence --------------------------------
// 4 clusters (1 per batch) x 8 CTAs x 384 threads.
// CTA rank owns hidden columns [rank*32, rank*32+32).
// Handoff: gate warp stages 32 h values in smem; lanes 0..7 each push one
// float4 to ALL 8 CTAs via st.shared::cluster.v4 + mbarrier.arrive.release
// (same thread => the release orders exactly the data it covers).
// Count-64 barriers (8 CTAs x 8 lanes), double-buffered, auto-rearm.
__device__ __forceinline__ void mbar_wait_acq(unsigned mb, unsigned parity)
{
    asm volatile(
        "{\n\t"
        ".reg .pred P;\n\t"
        "WL%=:\n\t"
        "mbarrier.try_wait.parity.acquire.cluster.shared::cta.b64 P, [%0], %1;\n\t"
        "@!P bra WL%=;\n\t"
        "}"
        :: "r"(mb), "r"(parity) : "memory");
}

__global__ void __launch_bounds__(384, 1) __cluster_dims__(8, 1, 1)
gru_kernel(const float* __restrict__ W_hh, const float* __restrict__ b_hh)
{
    __shared__ float  sh[2][HH];     // double-buffered h
    __shared__ float4 spart[96];     // partial dots [g*32 + col].kc
    __shared__ float  sstage[32];    // gate-warp h staging
    __shared__ alignas(8) unsigned long long mbars[2];

    const int tid  = threadIdx.x;
    const int w    = tid >> 5;       // 0..11
    const int lane = tid & 31;
    const int g    = w >> 2;         // gate 0..2
    const int kc   = w & 3;          // k-chunk 0..3
    unsigned rank;
    asm("mov.u32 %0, %%cluster_ctarank;" : "=r"(rank));
    const int batch = blockIdx.x >> 3;
    const int col   = (int)rank * 32 + lane;

    // persistent W_hh slice in registers, packed as f32x2 pairs
    unsigned long long wreg[32];
    {
        const ulonglong2* wp =
            (const ulonglong2*)(W_hh + (size_t)(g * HH + col) * HH + kc * 64);
#pragma unroll
        for (int i = 0; i < 16; i++) {
            const ulonglong2 wv = wp[i];
            wreg[2 * i + 0] = wv.x;
            wreg[2 * i + 1] = wv.y;
        }
    }

    float bhr = 0.f, bhz = 0.f, bhn = 0.f;
    int gcol = 0;
    if (tid < 32) {
        gcol = (int)rank * 32 + tid;
        bhr = b_hh[0 * HH + gcol];
        bhz = b_hh[1 * HH + gcol];
        bhn = b_hh[2 * HH + gcol];
    }

    const unsigned sh_addr = (unsigned)__cvta_generic_to_shared(&sh[0][0]);
    const unsigned mb_addr = (unsigned)__cvta_generic_to_shared(&mbars[0]);

    // hoisted remote addresses (lanes 0..7): data base (buffer 0, this lane's
    // float4 within our rank's 32-col slice) and barrier base, per dest CTA
    unsigned rem_d0[8], rem_m0[8];
    if (tid < 8) {
        const unsigned dbase = sh_addr + ((unsigned)rank * 32u + (unsigned)tid * 4u) * 4u;
#pragma unroll
        for (int rk = 0; rk < 8; rk++) {
            asm volatile("mapa.shared::cluster.u32 %0, %1, %2;"
                         : "=r"(rem_d0[rk]) : "r"(dbase), "r"((unsigned)rk));
            asm volatile("mapa.shared::cluster.u32 %0, %1, %2;"
                         : "=r"(rem_m0[rk]) : "r"(mb_addr), "r"((unsigned)rk));
        }
    }

    // init: h0 = 0, count-64 mbarriers (8 CTAs x 8 lanes, auto-rearm)
    if (tid < HH) sh[0][tid] = 0.f;
    if (tid == 0) {
        asm volatile("mbarrier.init.shared.b64 [%0], 64;" :: "r"(mb_addr)     : "memory");
        asm volatile("mbarrier.init.shared.b64 [%0], 64;" :: "r"(mb_addr + 8) : "memory");
    }
    __syncthreads();
    // all CTAs' mbarriers initialized before any remote arrive can land
    asm volatile("barrier.cluster.arrive.aligned;" ::: "memory");
    asm volatile("barrier.cluster.wait.aligned;"   ::: "memory");

    unsigned par0 = 0, par1 = 0;

    for (int t = 1; t <= SS; t++) {
        const int cur = (t - 1) & 1;
        const int nxt = t & 1;

        // xp loads issued BEFORE the wait (latency hidden)
        float xr = 0.f, xz = 0.f, xn = 0.f;
        if (tid < 32) {
            const size_t base = (size_t)(batch * SS + t - 1) * 768 + gcol;
            xr = g_xp[base + 0 * HH];
            xz = g_xp[base + 1 * HH];
            xn = g_xp[base + 2 * HH];
        }

        if (t > 1) {
            const unsigned mb = mb_addr + (unsigned)cur * 8u;
            mbar_wait_acq(mb, cur ? par1 : par0);
            if (cur) par1 ^= 1u; else par0 ^= 1u;
        }

        // partial dot: packed f32x2, two accumulators
        {
            const float* hb = &sh[cur][kc * 64];
            unsigned long long a0 = 0ULL, a1 = 0ULL;
#pragma unroll
            for (int i = 0; i < 64; i += 8) {
                const ulonglong2 h0 = *(const ulonglong2*)(hb + i);
                const ulonglong2 h1 = *(const ulonglong2*)(hb + i + 4);
                asm("fma.rn.f32x2 %0, %1, %2, %0;"
                    : "+l"(a0) : "l"(wreg[i / 2 + 0]), "l"(h0.x));
                asm("fma.rn.f32x2 %0, %1, %2, %0;"
                    : "+l"(a1) : "l"(wreg[i / 2 + 1]), "l"(h0.y));
                asm("fma.rn.f32x2 %0, %1, %2, %0;"
                    : "+l"(a0) : "l"(wreg[i / 2 + 2]), "l"(h1.x));
                asm("fma.rn.f32x2 %0, %1, %2, %0;"
                    : "+l"(a1) : "l"(wreg[i / 2 + 3]), "l"(h1.y));
            }
            const float s = __uint_as_float((unsigned)(a0 & 0xffffffffu))
                          + __uint_as_float((unsigned)(a0 >> 32))
                          + __uint_as_float((unsigned)(a1 & 0xffffffffu))
                          + __uint_as_float((unsigned)(a1 >> 32));
            ((float*)&spart[g * 32 + lane])[kc] = s;
        }
        __syncthreads();   // spart visible; all reads of sh done before handoff

        if (tid < 32) {    // gate warp
            const float4 p0 = spart[0 * 32 + tid];
            const float4 p1 = spart[1 * 32 + tid];
            const float4 p2 = spart[2 * 32 + tid];
            const float hr = p0.x + p0.y + p0.z + p0.w + bhr;
            const float hz = p1.x + p1.y + p1.z + p1.w + bhz;
            const float hn = p2.x + p2.y + p2.z + p2.w + bhn;
            const float r  = 1.f / (1.f + __expf(-(xr + hr)));
            const float z  = 1.f / (1.f + __expf(-(xz + hz)));
            const float nv = xn + r * hn;
            const float n  = 1.f - 2.f / (__expf(2.f * nv) + 1.f);   // tanh
            const float ho = sh[cur][gcol];
            const float hnew = (1.f - z) * n + z * ho;

            sstage[tid] = hnew;
            // GEMM copy: rounded to TF32 (RNA) + k-permuted
            g_hsR[(size_t)(batch * SS + t - 1) * HH + permk(gcol)] = rna_tf32(hnew);
            __syncwarp(0xffffffffu);

            if (tid < 8) {
                const float4 hv = *(const float4*)&sstage[tid * 4];
                const unsigned doff = (unsigned)(nxt * HH) * 4u;
                const unsigned moff = (unsigned)nxt * 8u;
#pragma unroll
                for (int rk = 0; rk < 8; rk++) {
                    asm volatile("st.shared::cluster.v4.f32 [%0], {%1,%2,%3,%4};"
                                 :: "r"(rem_d0[rk] + doff),
                                    "f"(hv.x), "f"(hv.y), "f"(hv.z), "f"(hv.w)
                                 : "memory");
                    asm volatile("mbarrier.arrive.release.cluster.shared::cluster.b64 _, [%0];"
                                 :: "r"(rem_m0[rk] + moff) : "memory");
                }
            }
        }
    }
    // drain: t=512 deliveries land on mbar[0]; no CTA exits while peer
    // stores into its smem are in flight
    mbar_wait_acq(mb_addr, par0);
}

// ---------------- kernel D: output GEMM (TF32 mma, permuted 128-bit LDS) ---
__device__ __forceinline__ void cp16(unsigned smem_dst, const void* gsrc) {
    asm volatile("cp.async.cg.shared.global [%0], [%1], 16;"
                 :: "r"(smem_dst), "l"(gsrc) : "memory");
}
__device__ __forceinline__ void mma_tf32(float* d, unsigned a0, unsigned a1,
                                         unsigned a2, unsigned a3,
                                         unsigned b0, unsigned b1) {
    asm volatile(
        "mma.sync.aligned.m16n8k8.row.col.f32.tf32.tf32.f32 "
        "{%0,%1,%2,%3}, {%4,%5,%6,%7}, {%8,%9}, {%0,%1,%2,%3};"
        : "+f"(d[0]), "+f"(d[1]), "+f"(d[2]), "+f"(d[3])
        : "r"(a0), "r"(a1), "r"(a2), "r"(a3), "r"(b0), "r"(b1));
}

__global__ void __launch_bounds__(256, 2) gemm_out_kernel(
    const float* __restrict__ bout, const int* __restrict__ x,
    float* __restrict__ out)
{
    __shared__ unsigned sA[2][128 * 16];   // 8 KB per stage
    __shared__ unsigned sB[2][128 * 16];

    const int m0   = blockIdx.y * 128;
    const int n0   = blockIdx.x * 128;
    const int tid  = threadIdx.x;
    const int lane = tid & 31;
    const int wid  = tid >> 5;          // 0..7
    const int wm   = wid & 3;           // 4 warps along m
    const int wn   = wid >> 2;          // 2 warps along n
    const int gid  = lane >> 2;
    const int tig  = lane & 3;

    float acc[2][8][4];
#pragma unroll
    for (int mi = 0; mi < 2; mi++)
#pragma unroll
        for (int ni = 0; ni < 8; ni++)
#pragma unroll
            for (int q = 0; q < 4; q++) acc[mi][ni][q] = 0.f;

    const int seg0 = tid * 2;
    const unsigned sA0 = (unsigned)__cvta_generic_to_shared(&sA[0][0]);
    const unsigned sB0 = (unsigned)__cvta_generic_to_shared(&sB[0][0]);

    // prefetch chunk 0 into stage 0
#pragma unroll
    for (int q = 0; q < 2; q++) {
        const int idx = seg0 + q;
        const int row = idx >> 2, quad = idx & 3;
        cp16(sA0 + (unsigned)(row * 16 + quad * 4) * 4u,
             g_hsR + (size_t)(m0 + row) * HH + quad * 4);
        cp16(sB0 + (unsigned)(row * 16 + quad * 4) * 4u,
             g_WoutR + (size_t)(n0 + row) * HH + quad * 4);
    }
    asm volatile("cp.async.commit_group;" ::: "memory");

    for (int c = 0; c < 16; c++) {
        const int s = c & 1;
        if (c + 1 < 16) {
            const unsigned so = (unsigned)((c + 1) & 1) * (128 * 16 * 4);
            const int k0 = (c + 1) * 16;
#pragma unroll
            for (int q = 0; q < 2; q++) {
                const int idx = seg0 + q;
                const int row = idx >> 2, quad = idx & 3;
                cp16(sA0 + so + (unsigned)(row * 16 + quad * 4) * 4u,
                     g_hsR + (size_t)(m0 + row) * HH + k0 + quad * 4);
                cp16(sB0 + so + (unsigned)(row * 16 + quad * 4) * 4u,
                     g_WoutR + (size_t)(n0 + row) * HH + k0 + quad * 4);
            }
            asm volatile("cp.async.commit_group;" ::: "memory");
            asm volatile("cp.async.wait_group 1;" ::: "memory");
        } else {
            asm volatile("cp.async.wait_group 0;" ::: "memory");
        }
        __syncthreads();

        uint4 av[2][2];
#pragma unroll
        for (int mi = 0; mi < 2; mi++) {
            const int base = wm * 32 + mi * 16;
            av[mi][0] = *(const uint4*)&sA[s][(base + gid) * 16 + tig * 4];
            av[mi][1] = *(const uint4*)&sA[s][(base + gid + 8) * 16 + tig * 4];
        }
#pragma unroll
        for (int nip = 0; nip < 4; nip++) {
            uint4 bv[2];
#pragma unroll
            for (int nj = 0; nj < 2; nj++) {
                const int nb = wn * 64 + (nip * 2 + nj) * 8;
                bv[nj] = *(const uint4*)&sB[s][(nb + gid) * 16 + tig * 4];
            }
            const unsigned* b0p = (const unsigned*)&bv[0];
            const unsigned* b1p = (const unsigned*)&bv[1];
#pragma unroll
            for (int ks = 0; ks < 2; ks++) {
#pragma unroll
                for (int mi = 0; mi < 2; mi++) {
                    const unsigned* r0 = (const unsigned*)&av[mi][0];
                    const unsigned* r1 = (const unsigned*)&av[mi][1];
                    mma_tf32(acc[mi][nip * 2 + 0],
                             r0[2 * ks], r1[2 * ks], r0[2 * ks + 1], r1[2 * ks + 1],
                             b0p[2 * ks], b0p[2 * ks + 1]);
                    mma_tf32(acc[mi][nip * 2 + 1],
                             r0[2 * ks], r1[2 * ks], r0[2 * ks + 1], r1[2 * ks + 1],
                             b1p[2 * ks], b1p[2 * ks + 1]);
                }
            }
        }
        __syncthreads();
    }

    // epilogue: bias + symbolic mask + store
#pragma unroll
    for (int mi = 0; mi < 2; mi++) {
        const int rbase = m0 + wm * 32 + mi * 16;
#pragma unroll
        for (int half = 0; half < 2; half++) {
            const int row = rbase + gid + half * 8;    // bt
            const int t   = row & (SS - 1);
            const bool pz = (t > 0) && (x[row - 1] == 0);
#pragma unroll
            for (int ni = 0; ni < 8; ni++) {
                const int col = n0 + wn * 64 + ni * 8 + tig * 2;
                float v0 = acc[mi][ni][half * 2 + 0] + bout[col];
                float v1 = acc[mi][ni][half * 2 + 1] + bout[col + 1];
                if (pz) {
                    if (col >= 3)     v0 = -INFINITY;
                    if (col + 1 >= 3) v1 = -INFINITY;
                }
                *(float2*)(out + (size_t)row * VV + col) = make_float2(v0, v1);
            }
        }
    }
}

// ---------------- launch ---------------------------------------------------
extern "C" void kernel_launch(void* const* d_in, const int* in_sizes, int n_in,
                              void* d_out, int out_size)
{
    const int*   x     = (const int*)  d_in[0];
    const float* emb   = (const float*)d_in[1];
    const float* W_ih  = (const float*)d_in[2];
    const float* W_hh  = (const float*)d_in[3];
    const float* b_ih  = (const float*)d_in[4];
    const float* b_hh  = (const float*)d_in[5];
    const float* W_out = (const float*)d_in[6];
    const float* b_out = (const float*)d_in[7];
    float* out = (float*)d_out;

    gather_kernel<<<MM, 64>>>(x, emb);
    roundw_kernel<<<VV, 256>>>(W_out);
    inproj_kernel<<<dim3(MM / 256, 768 / 16), 256>>>(W_ih, b_ih);
    gru_kernel<<<32, 384>>>(W_hh, b_hh);
    gemm_out_kernel<<<dim3(VV / 128, MM / 128), 256>>>(b_out, x, out);
}

// round 8
// speedup vs baseline: 1.6368x; 1.6368x over previous
#include <cuda_runtime.h>
#include <math.h>

#define BB   4
#define SS   512
#define HH   256
#define VV   32000
#define MM   (BB*SS)     // 2048
#define NTILES 4000      // 16 m-tiles x 250 n-tiles

// ---------------- device scratch (no allocation anywhere) ----------------
__device__ float    g_embT[HH * MM];            // [k][bt]                2 MB
__device__ float    g_xp[(size_t)MM * 768];     // [bt][row]              6 MB
__device__ float    g_hsR[(size_t)MM * HH];     // [bt][perm(k)] rounded  2 MB
__device__ float    g_WoutR[(size_t)VV * HH];   // [n][perm(k)] rounded  33 MB
__device__ unsigned g_prog[32];                 // [batch*8 + rank] = t done
__device__ unsigned g_ticket;                   // GEMM tile queue

// RNA round fp32 -> tf32 bit pattern (round-to-nearest, ties away)
__device__ __forceinline__ float rna_tf32(float v) {
    unsigned b = __float_as_uint(v);
    b = (b + 0x1000u) & 0xFFFFE000u;
    return __uint_as_float(b);
}
// permute k within 16-chunks (fragment-major for 128-bit LDS in the GEMM)
__device__ __forceinline__ int permk(int k) {
    return (k & ~15) | ((k & 3) << 2) | ((k >> 2) & 3);
}
__device__ __forceinline__ unsigned ld_acq_gpu(const unsigned* p) {
    unsigned v;
    asm volatile("ld.acquire.gpu.global.u32 %0, [%1];" : "=r"(v) : "l"(p) : "memory");
    return v;
}

// ---------------- kernel A: gather emb -> transposed + reset queue --------
__global__ void gather_kernel(const int* __restrict__ x,
                              const float* __restrict__ emb)
{
    const int bt  = blockIdx.x;
    const int tid = threadIdx.x;             // 0..63
    const int tok = x[bt];
    const float4 v = *(const float4*)(emb + (size_t)tok * HH + tid * 4);
    const int k = tid * 4;
    g_embT[(k + 0) * MM + bt] = v.x;
    g_embT[(k + 1) * MM + bt] = v.y;
    g_embT[(k + 2) * MM + bt] = v.z;
    g_embT[(k + 3) * MM + bt] = v.w;
    if (bt == 0) {
        if (tid < 32) g_prog[tid] = 0u;
        if (tid == 0) g_ticket = 0u;
    }
}

// ---------------- kernel B: xp = emb @ W_ih^T + b_ih ----------------------
__global__ void __launch_bounds__(256) inproj_kernel(
    const float* __restrict__ W_ih, const float* __restrict__ b_ih)
{
    __shared__ float sW[16 * 256];
    const int r0 = blockIdx.y * 16;
    const int bt = blockIdx.x * 256 + threadIdx.x;
    for (int i = threadIdx.x; i < 16 * 256; i += 256)
        sW[i] = W_ih[(size_t)r0 * 256 + i];
    __syncthreads();

    float acc[16];
#pragma unroll
    for (int ri = 0; ri < 16; ri++) acc[ri] = 0.f;

#pragma unroll 4
    for (int k = 0; k < HH; k++) {
        const float e = g_embT[k * MM + bt];
#pragma unroll
        for (int ri = 0; ri < 16; ri++)
            acc[ri] += e * sW[ri * 256 + k];
    }
    float* o = g_xp + (size_t)bt * 768 + r0;
#pragma unroll
    for (int ri = 0; ri < 16; ri++)
        o[ri] = acc[ri] + b_ih[r0 + ri];
}

// ---------------- kernel B2: round + permute W_out -------------------------
__global__ void __launch_bounds__(256) roundw_kernel(const float* __restrict__ Wout)
{
    const int n = blockIdx.x;
    const int k = threadIdx.x;
    g_WoutR[(size_t)n * HH + permk(k)] = rna_tf32(Wout[(size_t)n * HH + k]);
}

// ---------------- GEMM helpers ---------------------------------------------
__device__ __forceinline__ void cp16(unsigned smem_dst, const void* gsrc) {
    asm volatile("cp.async.cg.shared.global [%0], [%1], 16;"
                 :: "r"(smem_dst), "l"(gsrc) : "memory");
}
__device__ __forceinline__ void mma_tf32(float* d, unsigned a0, unsigned a1,
                                         unsigned a2, unsigned a3,
                                         unsigned b0, unsigned b1) {
    asm volatile(
        "mma.sync.aligned.m16n8k8.row.col.f32.tf32.tf32.f32 "
        "{%0,%1,%2,%3}, {%4,%5,%6,%7}, {%8,%9}, {%0,%1,%2,%3};"
        : "+f"(d[0]), "+f"(d[1]), "+f"(d[2]), "+f"(d[3])
        : "r"(a0), "r"(a1), "r"(a2), "r"(a3), "r"(b0), "r"(b1));
}

// ---------------- fused persistent kernel ----------------------------------
// Grid 144 CTAs x 384 thr, cluster 8 -> all co-resident (1 CTA/SM).
// CTAs 0..31 : GRU (4 clusters of 8, one per batch), R5 scheme + progress pub.
// CTAs 32..143 + finished GRU CTAs: GEMM tiles from atomic ticket queue,
// gated on GRU progress counters.
__global__ void __launch_bounds__(384, 1) __cluster_dims__(8, 1, 1)
fused_kernel(const float* __restrict__ W_hh, const float* __restrict__ b_hh,
             const float* __restrict__ bout, const int* __restrict__ x,
             float* __restrict__ out)
{
    __shared__ union {
        struct { float sh[2][HH]; float4 spart[96]; } r;           // GRU
        struct { unsigned sA[2][128 * 16]; unsigned sB[2][128 * 16]; } g; // GEMM
    } smem;
    __shared__ int s_ticket;

    const int tid  = threadIdx.x;
    const int cta  = blockIdx.x;
    const int lane = tid & 31;

    if (cta < 32) {
        // =================== GRU (R5 body, verbatim + progress) ===========
        const int w  = tid >> 5;       // 0..11
        const int g  = w >> 2;         // gate 0..2
        const int kc = w & 3;          // k-chunk 0..3
        unsigned rank;
        asm("mov.u32 %0, %%cluster_ctarank;" : "=r"(rank));
        const int batch = cta >> 3;
        const int col   = (int)rank * 32 + lane;

        unsigned long long wreg[32];
        {
            const ulonglong2* wp =
                (const ulonglong2*)(W_hh + (size_t)(g * HH + col) * HH + kc * 64);
#pragma unroll
            for (int i = 0; i < 16; i++) {
                const ulonglong2 wv = wp[i];
                wreg[2 * i + 0] = wv.x;
                wreg[2 * i + 1] = wv.y;
            }
        }

        float bhr = 0.f, bhz = 0.f, bhn = 0.f;
        int gcol = 0;
        if (tid < 32) {
            gcol = (int)rank * 32 + tid;
            bhr = b_hh[0 * HH + gcol];
            bhz = b_hh[1 * HH + gcol];
            bhn = b_hh[2 * HH + gcol];
        }

        const unsigned sh_addr = (unsigned)__cvta_generic_to_shared(&smem.r.sh[0][0]);

        if (tid < HH) smem.r.sh[0][tid] = 0.f;
        __syncthreads();
        asm volatile("barrier.cluster.arrive.aligned;" ::: "memory");

        for (int t = 1; t <= SS; t++) {
            const int cur = (t - 1) & 1;
            const int nxt = t & 1;

            float xr = 0.f, xz = 0.f, xn = 0.f;
            if (tid < 32) {
                const size_t base = (size_t)(batch * SS + t - 1) * 768 + gcol;
                xr = g_xp[base + 0 * HH];
                xz = g_xp[base + 1 * HH];
                xn = g_xp[base + 2 * HH];
            }

            asm volatile("barrier.cluster.wait.aligned;" ::: "memory");

            {
                const float* hb = &smem.r.sh[cur][kc * 64];
                unsigned long long a0 = 0ULL, a1 = 0ULL;
#pragma unroll
                for (int i = 0; i < 64; i += 8) {
                    const ulonglong2 h0 = *(const ulonglong2*)(hb + i);
                    const ulonglong2 h1 = *(const ulonglong2*)(hb + i + 4);
                    asm("fma.rn.f32x2 %0, %1, %2, %0;"
                        : "+l"(a0) : "l"(wreg[i / 2 + 0]), "l"(h0.x));
                    asm("fma.rn.f32x2 %0, %1, %2, %0;"
                        : "+l"(a1) : "l"(wreg[i / 2 + 1]), "l"(h0.y));
                    asm("fma.rn.f32x2 %0, %1, %2, %0;"
                        : "+l"(a0) : "l"(wreg[i / 2 + 2]), "l"(h1.x));
                    asm("fma.rn.f32x2 %0, %1, %2, %0;"
                        : "+l"(a1) : "l"(wreg[i / 2 + 3]), "l"(h1.y));
                }
                const float s = __uint_as_float((unsigned)(a0 & 0xffffffffu))
                              + __uint_as_float((unsigned)(a0 >> 32))
                              + __uint_as_float((unsigned)(a1 & 0xffffffffu))
                              + __uint_as_float((unsigned)(a1 >> 32));
                ((float*)&smem.r.spart[g * 32 + lane])[kc] = s;
            }
            __syncthreads();

            if (tid < 32) {
                const float4 p0 = smem.r.spart[0 * 32 + tid];
                const float4 p1 = smem.r.spart[1 * 32 + tid];
                const float4 p2 = smem.r.spart[2 * 32 + tid];
                const float hr = p0.x + p0.y + p0.z + p0.w + bhr;
                const float hz = p1.x + p1.y + p1.z + p1.w + bhz;
                const float hn = p2.x + p2.y + p2.z + p2.w + bhn;
                const float r  = 1.f / (1.f + __expf(-(xr + hr)));
                const float z  = 1.f / (1.f + __expf(-(xz + hz)));
                const float nv = xn + r * hn;
                const float n  = 1.f - 2.f / (__expf(2.f * nv) + 1.f);   // tanh
                const float ho = smem.r.sh[cur][gcol];
                const float hnew = (1.f - z) * n + z * ho;

                const unsigned dst = sh_addr + (unsigned)(nxt * HH + gcol) * 4u;
#pragma unroll
                for (int rk = 0; rk < 8; rk++) {
                    unsigned rem;
                    asm volatile("mapa.shared::cluster.u32 %0, %1, %2;"
                                 : "=r"(rem) : "r"(dst), "r"((unsigned)rk));
                    asm volatile("st.shared::cluster.f32 [%0], %1;"
                                 :: "r"(rem), "f"(hnew) : "memory");
                }
                // GEMM copy: rounded TF32 (RNA) + k-permuted
                g_hsR[(size_t)(batch * SS + t - 1) * HH + permk(gcol)] = rna_tf32(hnew);

                __syncwarp(0xffffffffu);
                if (tid == 0) {
                    // publish progress at gpu scope (covers all 32 lanes'
                    // stores via the syncwarp ordering edge)
                    asm volatile("red.release.gpu.global.max.u32 [%0], %1;"
                                 :: "l"(&g_prog[batch * 8 + (int)rank]),
                                    "r"((unsigned)t) : "memory");
                }
            }
            asm volatile("barrier.cluster.arrive.aligned;" ::: "memory");
        }
        asm volatile("barrier.cluster.wait.aligned;" ::: "memory");
        __syncthreads();   // smem union handoff: recurrence done, reuse as GEMM
    }

    // =================== GEMM ticket loop ==================================
    const int wid  = tid >> 5;          // 0..11 (compute uses 0..7)
    const int wm   = wid & 3;
    const int wn   = (wid >> 2) & 1;
    const int gid  = lane >> 2;
    const int tig  = lane & 3;
    const bool comp = (tid < 256);

    const unsigned sA0 = (unsigned)__cvta_generic_to_shared(&smem.g.sA[0][0]);
    const unsigned sB0 = (unsigned)__cvta_generic_to_shared(&smem.g.sB[0][0]);
    const int seg0 = tid * 2;           // only meaningful for comp threads

    for (;;) {
        if (tid == 0) s_ticket = (int)atomicAdd(&g_ticket, 1u);
        __syncthreads();
        const int tau = s_ticket;
        if (tau >= NTILES) break;

        const int j  = tau / 1000;              // m-chunk within a batch (0..3)
        const int rr = tau - j * 1000;
        const int b  = rr / 250;                // batch
        const int nt = rr - b * 250;            // n-tile
        const int m0 = b * 512 + j * 128;
        const int n0 = nt * 128;

        // gate on GRU progress: need t >= 128*(j+1) from all 8 rank counters
        if (tid < 8) {
            const unsigned T = 128u * (unsigned)(j + 1);
            while (ld_acq_gpu(&g_prog[b * 8 + tid]) < T) __nanosleep(128);
        }
        __syncthreads();

        float acc[2][8][4];
#pragma unroll
        for (int mi = 0; mi < 2; mi++)
#pragma unroll
            for (int ni = 0; ni < 8; ni++)
#pragma unroll
                for (int q = 0; q < 4; q++) acc[mi][ni][q] = 0.f;

        // prefetch chunk 0 into stage 0
        if (comp) {
#pragma unroll
            for (int q = 0; q < 2; q++) {
                const int idx = seg0 + q;
                const int row = idx >> 2, quad = idx & 3;
                cp16(sA0 + (unsigned)(row * 16 + quad * 4) * 4u,
                     g_hsR + (size_t)(m0 + row) * HH + quad * 4);
                cp16(sB0 + (unsigned)(row * 16 + quad * 4) * 4u,
                     g_WoutR + (size_t)(n0 + row) * HH + quad * 4);
            }
        }
        asm volatile("cp.async.commit_group;" ::: "memory");

        for (int c = 0; c < 16; c++) {
            const int s = c & 1;
            if (c + 1 < 16) {
                if (comp) {
                    const unsigned so = (unsigned)((c + 1) & 1) * (128 * 16 * 4);
                    const int k0 = (c + 1) * 16;
#pragma unroll
                    for (int q = 0; q < 2; q++) {
                        const int idx = seg0 + q;
                        const int row = idx >> 2, quad = idx & 3;
                        cp16(sA0 + so + (unsigned)(row * 16 + quad * 4) * 4u,
                             g_hsR + (size_t)(m0 + row) * HH + k0 + quad * 4);
                        cp16(sB0 + so + (unsigned)(row * 16 + quad * 4) * 4u,
                             g_WoutR + (size_t)(n0 + row) * HH + k0 + quad * 4);
                    }
                }
                asm volatile("cp.async.commit_group;" ::: "memory");
                asm volatile("cp.async.wait_group 1;" ::: "memory");
            } else {
                asm volatile("cp.async.wait_group 0;" ::: "memory");
            }
            __syncthreads();

            if (comp) {
                uint4 av[2][2];
#pragma unroll
                for (int mi = 0; mi < 2; mi++) {
                    const int base = wm * 32 + mi * 16;
                    av[mi][0] = *(const uint4*)&smem.g.sA[s][(base + gid) * 16 + tig * 4];
                    av[mi][1] = *(const uint4*)&smem.g.sA[s][(base + gid + 8) * 16 + tig * 4];
                }
#pragma unroll
                for (int nip = 0; nip < 4; nip++) {
                    uint4 bv[2];
#pragma unroll
                    for (int nj = 0; nj < 2; nj++) {
                        const int nb = wn * 64 + (nip * 2 + nj) * 8;
                        bv[nj] = *(const uint4*)&smem.g.sB[s][(nb + gid) * 16 + tig * 4];
                    }
                    const unsigned* b0p = (const unsigned*)&bv[0];
                    const unsigned* b1p = (const unsigned*)&bv[1];
#pragma unroll
                    for (int ks = 0; ks < 2; ks++) {
#pragma unroll
                        for (int mi = 0; mi < 2; mi++) {
                            const unsigned* r0 = (const unsigned*)&av[mi][0];
                            const unsigned* r1 = (const unsigned*)&av[mi][1];
                            mma_tf32(acc[mi][nip * 2 + 0],
                                     r0[2 * ks], r1[2 * ks], r0[2 * ks + 1], r1[2 * ks + 1],
                                     b0p[2 * ks], b0p[2 * ks + 1]);
                            mma_tf32(acc[mi][nip * 2 + 1],
                                     r0[2 * ks], r1[2 * ks], r0[2 * ks + 1], r1[2 * ks + 1],
                                     b1p[2 * ks], b1p[2 * ks + 1]);
                        }
                    }
                }
            }
            __syncthreads();
        }

        // epilogue: bias + symbolic mask + store
        if (comp) {
#pragma unroll
            for (int mi = 0; mi < 2; mi++) {
                const int rbase = m0 + wm * 32 + mi * 16;
#pragma unroll
                for (int half = 0; half < 2; half++) {
                    const int row = rbase + gid + half * 8;    // bt
                    const int t   = row & (SS - 1);
                    const bool pz = (t > 0) && (x[row - 1] == 0);
#pragma unroll
                    for (int ni = 0; ni < 8; ni++) {
                        const int colx = n0 + wn * 64 + ni * 8 + tig * 2;
                        float v0 = acc[mi][ni][half * 2 + 0] + bout[colx];
                        float v1 = acc[mi][ni][half * 2 + 1] + bout[colx + 1];
                        if (pz) {
                            if (colx >= 3)     v0 = -INFINITY;
                            if (colx + 1 >= 3) v1 = -INFINITY;
                        }
                        *(float2*)(out + (size_t)row * VV + colx) = make_float2(v0, v1);
                    }
                }
            }
        }
        __syncthreads();   // everyone done with smem + s_ticket before next tile
    }
}

// ---------------- launch ---------------------------------------------------
extern "C" void kernel_launch(void* const* d_in, const int* in_sizes, int n_in,
                              void* d_out, int out_size)
{
    const int*   x     = (const int*)  d_in[0];
    const float* emb   = (const float*)d_in[1];
    const float* W_ih  = (const float*)d_in[2];
    const float* W_hh  = (const float*)d_in[3];
    const float* b_ih  = (const float*)d_in[4];
    const float* b_hh  = (const float*)d_in[5];
    const float* W_out = (const float*)d_in[6];
    const float* b_out = (const float*)d_in[7];
    float* out = (float*)d_out;

    gather_kernel<<<MM, 64>>>(x, emb);
    roundw_kernel<<<VV, 256>>>(W_out);
    inproj_kernel<<<dim3(MM / 256, 768 / 16), 256>>>(W_ih, b_ih);
    fused_kernel<<<144, 384>>>(W_hh, b_hh, b_out, x, out);
}

// round 10
// speedup vs baseline: 1.6678x; 1.0189x over previous
#include <cuda_runtime.h>
#include <math.h>

#define BB   4
#define SS   512
#define HH   256
#define VV   32000
#define MM   (BB*SS)     // 2048

// ---------------- device scratch (no allocation anywhere) ----------------
__device__ float g_embT[HH * MM];            // [k][bt]               2 MB
__device__ float g_xp[(size_t)MM * 768];     // [bt][row]             6 MB
__device__ float g_hsR[(size_t)MM * HH];     // [bt][k] RNA-rounded   2 MB
__device__ float g_WoutR[(size_t)VV * HH];   // [n][k] RNA-rounded   33 MB

// RNA round fp32 -> tf32 bit pattern (round-to-nearest, ties away)
__device__ __forceinline__ float rna_tf32(float v) {
    unsigned b = __float_as_uint(v);
    b = (b + 0x1000u) & 0xFFFFE000u;
    return __uint_as_float(b);
}

// ---------------- kernel A: gather emb -> transposed ----------------------
__global__ void gather_kernel(const int* __restrict__ x,
                              const float* __restrict__ emb)
{
    const int bt  = blockIdx.x;
    const int tid = threadIdx.x;             // 0..63
    const int tok = x[bt];
    const float4 v = *(const float4*)(emb + (size_t)tok * HH + tid * 4);
    const int k = tid * 4;
    g_embT[(k + 0) * MM + bt] = v.x;
    g_embT[(k + 1) * MM + bt] = v.y;
    g_embT[(k + 2) * MM + bt] = v.z;
    g_embT[(k + 3) * MM + bt] = v.w;
}

// ---------------- kernel B: xp = emb @ W_ih^T + b_ih ----------------------
__global__ void __launch_bounds__(256) inproj_kernel(
    const float* __restrict__ W_ih, const float* __restrict__ b_ih)
{
    __shared__ float sW[16 * 256];
    const int r0 = blockIdx.y * 16;
    const int bt = blockIdx.x * 256 + threadIdx.x;
    for (int i = threadIdx.x; i < 16 * 256; i += 256)
        sW[i] = W_ih[(size_t)r0 * 256 + i];
    __syncthreads();

    float acc[16];
#pragma unroll
    for (int ri = 0; ri < 16; ri++) acc[ri] = 0.f;

#pragma unroll 4
    for (int k = 0; k < HH; k++) {
        const float e = g_embT[k * MM + bt];
#pragma unroll
        for (int ri = 0; ri < 16; ri++)
            acc[ri] += e * sW[ri * 256 + k];
    }
    float* o = g_xp + (size_t)bt * 768 + r0;
#pragma unroll
    for (int ri = 0; ri < 16; ri++)
        o[ri] = acc[ri] + b_ih[r0 + ri];
}

// ---------------- kernel B2: RNA-round W_out -------------------------------
__global__ void __launch_bounds__(256) roundw_kernel(const float* __restrict__ Wout)
{
    const size_t i = (size_t)blockIdx.x * 256 + threadIdx.x;
    g_WoutR[i] = rna_tf32(Wout[i]);
}

// ---------------- kernel C: GRU recurrence (R5 scheme) ---------------------
// 4 clusters (1 per batch) x 8 CTAs x 384 threads; CTA owns cols [rank*32,+32).
__global__ void __launch_bounds__(384, 1) __cluster_dims__(8, 1, 1)
gru_kernel(const float* __restrict__ W_hh, const float* __restrict__ b_hh)
{
    __shared__ float  sh[2][HH];     // double-buffered h for this batch
    __shared__ float4 spart[96];     // partial dots [g*32 + col].kc

    const int tid  = threadIdx.x;
    const int w    = tid >> 5;       // 0..11
    const int lane = tid & 31;
    const int g    = w >> 2;         // gate 0..2
    const int kc   = w & 3;          // k-chunk 0..3
    unsigned rank;
    asm("mov.u32 %0, %%cluster_ctarank;" : "=r"(rank));
    const int batch = blockIdx.x >> 3;
    const int col   = (int)rank * 32 + lane;

    // persistent W_hh slice in registers, packed as f32x2 pairs
    unsigned long long wreg[32];
    {
        const ulonglong2* wp =
            (const ulonglong2*)(W_hh + (size_t)(g * HH + col) * HH + kc * 64);
#pragma unroll
        for (int i = 0; i < 16; i++) {
            const ulonglong2 wv = wp[i];
            wreg[2 * i + 0] = wv.x;
            wreg[2 * i + 1] = wv.y;
        }
    }

    float bhr = 0.f, bhz = 0.f, bhn = 0.f;
    int gcol = 0;
    if (tid < 32) {
        gcol = (int)rank * 32 + tid;
        bhr = b_hh[0 * HH + gcol];
        bhz = b_hh[1 * HH + gcol];
        bhn = b_hh[2 * HH + gcol];
    }

    const unsigned sh_addr = (unsigned)__cvta_generic_to_shared(&sh[0][0]);

    if (tid < HH) sh[0][tid] = 0.f;
    __syncthreads();
    asm volatile("barrier.cluster.arrive.aligned;" ::: "memory");

    for (int t = 1; t <= SS; t++) {
        const int cur = (t - 1) & 1;
        const int nxt = t & 1;

        // xp loads issued BEFORE the barrier wait (latency hidden)
        float xr = 0.f, xz = 0.f, xn = 0.f;
        if (tid < 32) {
            const size_t base = (size_t)(batch * SS + t - 1) * 768 + gcol;
            xr = g_xp[base + 0 * HH];
            xz = g_xp[base + 1 * HH];
            xn = g_xp[base + 2 * HH];
        }

        asm volatile("barrier.cluster.wait.aligned;" ::: "memory");

        // partial dot: packed f32x2, two accumulators
        {
            const float* hb = &sh[cur][kc * 64];
            unsigned long long a0 = 0ULL, a1 = 0ULL;
#pragma unroll
            for (int i = 0; i < 64; i += 8) {
                const ulonglong2 h0 = *(const ulonglong2*)(hb + i);
                const ulonglong2 h1 = *(const ulonglong2*)(hb + i + 4);
                asm("fma.rn.f32x2 %0, %1, %2, %0;"
                    : "+l"(a0) : "l"(wreg[i / 2 + 0]), "l"(h0.x));
                asm("fma.rn.f32x2 %0, %1, %2, %0;"
                    : "+l"(a1) : "l"(wreg[i / 2 + 1]), "l"(h0.y));
                asm("fma.rn.f32x2 %0, %1, %2, %0;"
                    : "+l"(a0) : "l"(wreg[i / 2 + 2]), "l"(h1.x));
                asm("fma.rn.f32x2 %0, %1, %2, %0;"
                    : "+l"(a1) : "l"(wreg[i / 2 + 3]), "l"(h1.y));
            }
            const float s = __uint_as_float((unsigned)(a0 & 0xffffffffu))
                          + __uint_as_float((unsigned)(a0 >> 32))
                          + __uint_as_float((unsigned)(a1 & 0xffffffffu))
                          + __uint_as_float((unsigned)(a1 >> 32));
            ((float*)&spart[g * 32 + lane])[kc] = s;
        }
        __syncthreads();

        float hnew = 0.f;
        if (tid < 32) {
            const float4 p0 = spart[0 * 32 + tid];
            const float4 p1 = spart[1 * 32 + tid];
            const float4 p2 = spart[2 * 32 + tid];
            const float hr = p0.x + p0.y + p0.z + p0.w + bhr;
            const float hz = p1.x + p1.y + p1.z + p1.w + bhz;
            const float hn = p2.x + p2.y + p2.z + p2.w + bhn;
            const float r  = 1.f / (1.f + __expf(-(xr + hr)));
            const float z  = 1.f / (1.f + __expf(-(xz + hz)));
            const float nv = xn + r * hn;
            const float n  = 1.f - 2.f / (__expf(2.f * nv) + 1.f);   // tanh
            const float ho = sh[cur][gcol];
            hnew = (1.f - z) * n + z * ho;

            const unsigned dst = sh_addr + (unsigned)(nxt * HH + gcol) * 4u;
#pragma unroll
            for (int rk = 0; rk < 8; rk++) {
                unsigned rem;
                asm volatile("mapa.shared::cluster.u32 %0, %1, %2;"
                             : "=r"(rem) : "r"(dst), "r"((unsigned)rk));
                asm volatile("st.shared::cluster.f32 [%0], %1;"
                             :: "r"(rem), "f"(hnew) : "memory");
            }
        }

        // release our DSMEM stores; matching wait at top of next step
        asm volatile("barrier.cluster.arrive.aligned;" ::: "memory");

        // off critical path: GEMM copy (kernel boundary orders it vs GEMM)
        if (tid < 32)
            g_hsR[(size_t)(batch * SS + t - 1) * HH + gcol] = rna_tf32(hnew);
    }
    asm volatile("barrier.cluster.wait.aligned;" ::: "memory");
}

// ---------------- kernel D: output GEMM (TF32 mma, 64x128 tiles, 4 CTA/SM) -
#define LDP 20           // padded smem row stride (floats), conflict-free

__device__ __forceinline__ void cp16(unsigned smem_dst, const void* gsrc) {
    asm volatile("cp.async.cg.shared.global [%0], [%1], 16;"
                 :: "r"(smem_dst), "l"(gsrc) : "memory");
}
__device__ __forceinline__ void mma_tf32(float* d, unsigned a0, unsigned a1,
                                         unsigned a2, unsigned a3,
                                         unsigned b0, unsigned b1) {
    asm volatile(
        "mma.sync.aligned.m16n8k8.row.col.f32.tf32.tf32.f32 "
        "{%0,%1,%2,%3}, {%4,%5,%6,%7}, {%8,%9}, {%0,%1,%2,%3};"
        : "+f"(d[0]), "+f"(d[1]), "+f"(d[2]), "+f"(d[3])
        : "r"(a0), "r"(a1), "r"(a2), "r"(a3), "r"(b0), "r"(b1));
}

__global__ void __launch_bounds__(128, 4) gemm_out_kernel(
    const float* __restrict__ bout, const int* __restrict__ x,
    float* __restrict__ out)
{
    __shared__ unsigned sA[2][64 * LDP];    //  5 KB/stage
    __shared__ unsigned sB[2][128 * LDP];   // 10 KB/stage

    const int m0   = blockIdx.y * 64;
    const int n0   = blockIdx.x * 128;
    const int tid  = threadIdx.x;           // 0..127
    const int lane = tid & 31;
    const int wid  = tid >> 5;               // 0..3
    const int wm   = wid & 1;                // 2 warps along m (32 rows each)
    const int wn   = wid >> 1;               // 2 warps along n (64 cols each)
    const int gid  = lane >> 2;
    const int tig  = lane & 3;

    float acc[2][8][4];
#pragma unroll
    for (int mi = 0; mi < 2; mi++)
#pragma unroll
        for (int ni = 0; ni < 8; ni++)
#pragma unroll
            for (int q = 0; q < 4; q++) acc[mi][ni][q] = 0.f;

    const unsigned sA0 = (unsigned)__cvta_generic_to_shared(&sA[0][0]);
    const unsigned sB0 = (unsigned)__cvta_generic_to_shared(&sB[0][0]);

    // loaders: A = 256 segs (2/thr), B = 512 segs (4/thr); seg = 16B, 4/row
    // prefetch chunk 0 into stage 0
#pragma unroll
    for (int q = 0; q < 2; q++) {
        const int idx = tid * 2 + q;
        const int row = idx >> 2, quad = idx & 3;
        cp16(sA0 + (unsigned)(row * LDP + quad * 4) * 4u,
             g_hsR + (size_t)(m0 + row) * HH + quad * 4);
    }
#pragma unroll
    for (int q = 0; q < 4; q++) {
        const int idx = tid * 4 + q;
        const int row = idx >> 2, quad = idx & 3;
        cp16(sB0 + (unsigned)(row * LDP + quad * 4) * 4u,
             g_WoutR + (size_t)(n0 + row) * HH + quad * 4);
    }
    asm volatile("cp.async.commit_group;" ::: "memory");

    for (int c = 0; c < 16; c++) {
        const int s = c & 1;
        if (c + 1 < 16) {
            const unsigned soA = (unsigned)((c + 1) & 1) * (64 * LDP * 4);
            const unsigned soB = (unsigned)((c + 1) & 1) * (128 * LDP * 4);
            const int k0 = (c + 1) * 16;
#pragma unroll
            for (int q = 0; q < 2; q++) {
                const int idx = tid * 2 + q;
                const int row = idx >> 2, quad = idx & 3;
                cp16(sA0 + soA + (unsigned)(row * LDP + quad * 4) * 4u,
                     g_hsR + (size_t)(m0 + row) * HH + k0 + quad * 4);
            }
#pragma unroll
            for (int q = 0; q < 4; q++) {
                const int idx = tid * 4 + q;
                const int row = idx >> 2, quad = idx & 3;
                cp16(sB0 + soB + (unsigned)(row * LDP + quad * 4) * 4u,
                     g_WoutR + (size_t)(n0 + row) * HH + k0 + quad * 4);
            }
            asm volatile("cp.async.commit_group;" ::: "memory");
            asm volatile("cp.async.wait_group 1;" ::: "memory");
        } else {
            asm volatile("cp.async.wait_group 0;" ::: "memory");
        }
        __syncthreads();

#pragma unroll
        for (int ks = 0; ks < 2; ks++) {
            const int k8 = ks * 8;
            unsigned af[2][4];
#pragma unroll
            for (int mi = 0; mi < 2; mi++) {
                const int base = wm * 32 + mi * 16;
                af[mi][0] = sA[s][(base + gid) * LDP + k8 + tig];
                af[mi][1] = sA[s][(base + gid + 8) * LDP + k8 + tig];
                af[mi][2] = sA[s][(base + gid) * LDP + k8 + tig + 4];
                af[mi][3] = sA[s][(base + gid + 8) * LDP + k8 + tig + 4];
            }
#pragma unroll
            for (int ni = 0; ni < 8; ni++) {
                const int nb = wn * 64 + ni * 8;
                const unsigned b0 = sB[s][(nb + gid) * LDP + k8 + tig];
                const unsigned b1 = sB[s][(nb + gid) * LDP + k8 + tig + 4];
#pragma unroll
                for (int mi = 0; mi < 2; mi++) {
                    mma_tf32(acc[mi][ni],
                             af[mi][0], af[mi][1], af[mi][2], af[mi][3],
                             b0, b1);
                }
            }
        }
        __syncthreads();
    }

    // epilogue: bias + symbolic mask + store
#pragma unroll
    for (int mi = 0; mi < 2; mi++) {
        const int rbase = m0 + wm * 32 + mi * 16;
#pragma unroll
        for (int half = 0; half < 2; half++) {
            const int row = rbase + gid + half * 8;    // bt
            const int t   = row & (SS - 1);
            const bool pz = (t > 0) && (x[row - 1] == 0);
#pragma unroll
            for (int ni = 0; ni < 8; ni++) {
                const int col = n0 + wn * 64 + ni * 8 + tig * 2;
                float v0 = acc[mi][ni][half * 2 + 0] + bout[col];
                float v1 = acc[mi][ni][half * 2 + 1] + bout[col + 1];
                if (pz) {
                    if (col >= 3)     v0 = -INFINITY;
                    if (col + 1 >= 3) v1 = -INFINITY;
                }
                *(float2*)(out + (size_t)row * VV + col) = make_float2(v0, v1);
            }
        }
    }
}

// ---------------- launch ---------------------------------------------------
extern "C" void kernel_launch(void* const* d_in, const int* in_sizes, int n_in,
                              void* d_out, int out_size)
{
    const int*   x     = (const int*)  d_in[0];
    const float* emb   = (const float*)d_in[1];
    const float* W_ih  = (const float*)d_in[2];
    const float* W_hh  = (const float*)d_in[3];
    const float* b_ih  = (const float*)d_in[4];
    const float* b_hh  = (const float*)d_in[5];
    const float* W_out = (const float*)d_in[6];
    const float* b_out = (const float*)d_in[7];
    float* out = (float*)d_out;

    gather_kernel<<<MM, 64>>>(x, emb);
    roundw_kernel<<<(VV * HH) / 256, 256>>>(W_out);
    inproj_kernel<<<dim3(MM / 256, 768 / 16), 256>>>(W_ih, b_ih);
    gru_kernel<<<32, 384>>>(W_hh, b_hh);
    gemm_out_kernel<<<dim3(VV / 128, MM / 64), 128>>>(b_out, x, out);
}

// round 11
// speedup vs baseline: 1.7606x; 1.0557x over previous
#include <cuda_runtime.h>
#include <math.h>

#define BB   4
#define SS   512
#define HH   256
#define VV   32000
#define MM   (BB*SS)     // 2048

// ---------------- device scratch (no allocation anywhere) ----------------
__device__ float g_embT[HH * MM];            // [k][bt]               2 MB
__device__ float g_xp[(size_t)MM * 768];     // [bt][row]             6 MB
__device__ float g_hsR[(size_t)MM * HH];     // [bt][k] RNA-rounded   2 MB
__device__ float g_WoutR[(size_t)VV * HH];   // [n][k] RNA-rounded   33 MB
__device__ float g_hsave[BB * HH];           // h checkpoint between chunks

// ---------------- streams/events (static init: before harness baseline) ---
namespace {
struct OverlapRes {
    cudaStream_t lo;
    cudaEvent_t  ev[6];
    OverlapRes() {
        int least = 0, greatest = 0;
        cudaDeviceGetStreamPriorityRange(&least, &greatest);
        cudaStreamCreateWithPriority(&lo, cudaStreamNonBlocking, least);
        for (int i = 0; i < 6; i++)
            cudaEventCreateWithFlags(&ev[i], cudaEventDisableTiming);
    }
};
OverlapRes g_res;
}

// RNA round fp32 -> tf32 bit pattern (round-to-nearest, ties away)
__device__ __forceinline__ float rna_tf32(float v) {
    unsigned b = __float_as_uint(v);
    b = (b + 0x1000u) & 0xFFFFE000u;
    return __uint_as_float(b);
}

// ---------------- kernel A: gather emb -> transposed ----------------------
__global__ void gather_kernel(const int* __restrict__ x,
                              const float* __restrict__ emb)
{
    const int bt  = blockIdx.x;
    const int tid = threadIdx.x;             // 0..63
    const int tok = x[bt];
    const float4 v = *(const float4*)(emb + (size_t)tok * HH + tid * 4);
    const int k = tid * 4;
    g_embT[(k + 0) * MM + bt] = v.x;
    g_embT[(k + 1) * MM + bt] = v.y;
    g_embT[(k + 2) * MM + bt] = v.z;
    g_embT[(k + 3) * MM + bt] = v.w;
}

// ---------------- kernel B: xp = emb @ W_ih^T + b_ih ----------------------
__global__ void __launch_bounds__(256) inproj_kernel(
    const float* __restrict__ W_ih, const float* __restrict__ b_ih)
{
    __shared__ float sW[16 * 256];
    const int r0 = blockIdx.y * 16;
    const int bt = blockIdx.x * 256 + threadIdx.x;
    for (int i = threadIdx.x; i < 16 * 256; i += 256)
        sW[i] = W_ih[(size_t)r0 * 256 + i];
    __syncthreads();

    float acc[16];
#pragma unroll
    for (int ri = 0; ri < 16; ri++) acc[ri] = 0.f;

#pragma unroll 4
    for (int k = 0; k < HH; k++) {
        const float e = g_embT[k * MM + bt];
#pragma unroll
        for (int ri = 0; ri < 16; ri++)
            acc[ri] += e * sW[ri * 256 + k];
    }
    float* o = g_xp + (size_t)bt * 768 + r0;
#pragma unroll
    for (int ri = 0; ri < 16; ri++)
        o[ri] = acc[ri] + b_ih[r0 + ri];
}

// ---------------- kernel B2: RNA-round W_out -------------------------------
__global__ void __launch_bounds__(256) roundw_kernel(const float* __restrict__ Wout)
{
    const size_t i = (size_t)blockIdx.x * 256 + threadIdx.x;
    g_WoutR[i] = rna_tf32(Wout[i]);
}

// ---------------- kernel C: GRU recurrence chunk (R5 scheme, 128 steps) ----
// 4 clusters (1 per batch) x 8 CTAs x 384 threads; CTA owns cols [rank*32,+32).
// Runs steps t0+1 .. t0+128; h checkpointed in g_hsave between chunks.
__global__ void __launch_bounds__(384, 1) __cluster_dims__(8, 1, 1)
gru_kernel(const float* __restrict__ W_hh, const float* __restrict__ b_hh,
           const int t0)
{
    __shared__ float  sh[2][HH];     // double-buffered h for this batch
    __shared__ float4 spart[96];     // partial dots [g*32 + col].kc

    const int tid  = threadIdx.x;
    const int w    = tid >> 5;       // 0..11
    const int lane = tid & 31;
    const int g    = w >> 2;         // gate 0..2
    const int kc   = w & 3;          // k-chunk 0..3
    unsigned rank;
    asm("mov.u32 %0, %%cluster_ctarank;" : "=r"(rank));
    const int batch = blockIdx.x >> 3;
    const int col   = (int)rank * 32 + lane;

    // persistent W_hh slice in registers, packed as f32x2 pairs
    unsigned long long wreg[32];
    {
        const ulonglong2* wp =
            (const ulonglong2*)(W_hh + (size_t)(g * HH + col) * HH + kc * 64);
#pragma unroll
        for (int i = 0; i < 16; i++) {
            const ulonglong2 wv = wp[i];
            wreg[2 * i + 0] = wv.x;
            wreg[2 * i + 1] = wv.y;
        }
    }

    float bhr = 0.f, bhz = 0.f, bhn = 0.f;
    int gcol = 0;
    if (tid < 32) {
        gcol = (int)rank * 32 + tid;
        bhr = b_hh[0 * HH + gcol];
        bhz = b_hh[1 * HH + gcol];
        bhn = b_hh[2 * HH + gcol];
    }

    const unsigned sh_addr = (unsigned)__cvta_generic_to_shared(&sh[0][0]);

    // init sh[0] = h(t0): zeros for chunk 0, checkpoint otherwise
    if (tid < HH)
        sh[0][tid] = (t0 == 0) ? 0.f : g_hsave[batch * HH + tid];
    __syncthreads();
    asm volatile("barrier.cluster.arrive.aligned;" ::: "memory");

    const int tend = t0 + 128;
    for (int t = t0 + 1; t <= tend; t++) {
        const int cur = (t - 1) & 1;     // t0 even -> buffer 0 holds h(t0)
        const int nxt = t & 1;

        // xp loads issued BEFORE the barrier wait (latency hidden)
        float xr = 0.f, xz = 0.f, xn = 0.f;
        if (tid < 32) {
            const size_t base = (size_t)(batch * SS + t - 1) * 768 + gcol;
            xr = g_xp[base + 0 * HH];
            xz = g_xp[base + 1 * HH];
            xn = g_xp[base + 2 * HH];
        }

        asm volatile("barrier.cluster.wait.aligned;" ::: "memory");

        // partial dot: packed f32x2, two accumulators
        {
            const float* hb = &sh[cur][kc * 64];
            unsigned long long a0 = 0ULL, a1 = 0ULL;
#pragma unroll
            for (int i = 0; i < 64; i += 8) {
                const ulonglong2 h0 = *(const ulonglong2*)(hb + i);
                const ulonglong2 h1 = *(const ulonglong2*)(hb + i + 4);
                asm("fma.rn.f32x2 %0, %1, %2, %0;"
                    : "+l"(a0) : "l"(wreg[i / 2 + 0]), "l"(h0.x));
                asm("fma.rn.f32x2 %0, %1, %2, %0;"
                    : "+l"(a1) : "l"(wreg[i / 2 + 1]), "l"(h0.y));
                asm("fma.rn.f32x2 %0, %1, %2, %0;"
                    : "+l"(a0) : "l"(wreg[i / 2 + 2]), "l"(h1.x));
                asm("fma.rn.f32x2 %0, %1, %2, %0;"
                    : "+l"(a1) : "l"(wreg[i / 2 + 3]), "l"(h1.y));
            }
            const float s = __uint_as_float((unsigned)(a0 & 0xffffffffu))
                          + __uint_as_float((unsigned)(a0 >> 32))
                          + __uint_as_float((unsigned)(a1 & 0xffffffffu))
                          + __uint_as_float((unsigned)(a1 >> 32));
            ((float*)&spart[g * 32 + lane])[kc] = s;
        }
        __syncthreads();

        float hnew = 0.f;
        if (tid < 32) {
            const float4 p0 = spart[0 * 32 + tid];
            const float4 p1 = spart[1 * 32 + tid];
            const float4 p2 = spart[2 * 32 + tid];
            const float hr = p0.x + p0.y + p0.z + p0.w + bhr;
            const float hz = p1.x + p1.y + p1.z + p1.w + bhz;
            const float hn = p2.x + p2.y + p2.z + p2.w + bhn;
            const float r  = 1.f / (1.f + __expf(-(xr + hr)));
            const float z  = 1.f / (1.f + __expf(-(xz + hz)));
            const float nv = xn + r * hn;
            const float n  = 1.f - 2.f / (__expf(2.f * nv) + 1.f);   // tanh
            const float ho = sh[cur][gcol];
            hnew = (1.f - z) * n + z * ho;

            const unsigned dst = sh_addr + (unsigned)(nxt * HH + gcol) * 4u;
#pragma unroll
            for (int rk = 0; rk < 8; rk++) {
                unsigned rem;
                asm volatile("mapa.shared::cluster.u32 %0, %1, %2;"
                             : "=r"(rem) : "r"(dst), "r"((unsigned)rk));
                asm volatile("st.shared::cluster.f32 [%0], %1;"
                             :: "r"(rem), "f"(hnew) : "memory");
            }
        }

        // release our DSMEM stores; matching wait at top of next step
        asm volatile("barrier.cluster.arrive.aligned;" ::: "memory");

        // off critical path: GEMM copy (kernel boundary orders it vs GEMM)
        if (tid < 32) {
            g_hsR[(size_t)(batch * SS + t - 1) * HH + gcol] = rna_tf32(hnew);
            if (t == tend)
                g_hsave[batch * HH + gcol] = hnew;    // checkpoint for next chunk
        }
    }
    asm volatile("barrier.cluster.wait.aligned;" ::: "memory");
}

// ---------------- kernel D: output GEMM chunk (TF32 mma, 128x128) ---------
#define KCH  16          // k-chunk
#define LDP  20          // padded smem row stride (floats)

__device__ __forceinline__ void cp16(unsigned smem_dst, const void* gsrc) {
    asm volatile("cp.async.cg.shared.global [%0], [%1], 16;"
                 :: "r"(smem_dst), "l"(gsrc) : "memory");
}
__device__ __forceinline__ void mma_tf32(float* d, unsigned a0, unsigned a1,
                                         unsigned a2, unsigned a3,
                                         unsigned b0, unsigned b1) {
    asm volatile(
        "mma.sync.aligned.m16n8k8.row.col.f32.tf32.tf32.f32 "
        "{%0,%1,%2,%3}, {%4,%5,%6,%7}, {%8,%9}, {%0,%1,%2,%3};"
        : "+f"(d[0]), "+f"(d[1]), "+f"(d[2]), "+f"(d[3])
        : "r"(a0), "r"(a1), "r"(a2), "r"(a3), "r"(b0), "r"(b1));
}

__global__ void __launch_bounds__(256, 2) gemm_out_kernel(
    const float* __restrict__ bout, const int* __restrict__ x,
    float* __restrict__ out, const int j)
{
    __shared__ unsigned sA[2][128 * LDP];
    __shared__ unsigned sB[2][128 * LDP];

    const int m0   = blockIdx.y * 512 + j * 128;   // rows b*512 + [128j, +128)
    const int n0   = blockIdx.x * 128;
    const int tid  = threadIdx.x;
    const int lane = tid & 31;
    const int wid  = tid >> 5;          // 0..7
    const int wm   = wid & 3;           // 4 warps along m
    const int wn   = wid >> 2;          // 2 warps along n
    const int gid  = lane >> 2;
    const int tig  = lane & 3;

    float acc[2][8][4];
#pragma unroll
    for (int mi = 0; mi < 2; mi++)
#pragma unroll
        for (int ni = 0; ni < 8; ni++)
#pragma unroll
            for (int q = 0; q < 4; q++) acc[mi][ni][q] = 0.f;

    const int lrow = tid >> 2;
    const int lseg = (tid & 3) * 4;
    const unsigned sA0 = (unsigned)__cvta_generic_to_shared(&sA[0][0]);
    const unsigned sB0 = (unsigned)__cvta_generic_to_shared(&sB[0][0]);
    const unsigned stageBytes = 128 * LDP * 4;

    // prefetch chunk 0 into stage 0
#pragma unroll
    for (int p = 0; p < 2; p++) {
        const int row = p * 64 + lrow;
        cp16(sA0 + (unsigned)(row * LDP + lseg) * 4u,
             g_hsR + (size_t)(m0 + row) * HH + lseg);
        cp16(sB0 + (unsigned)(row * LDP + lseg) * 4u,
             g_WoutR + (size_t)(n0 + row) * HH + lseg);
    }
    asm volatile("cp.async.commit_group;" ::: "memory");

    for (int c = 0; c < HH / KCH; c++) {
        const int s = c & 1;
        if (c + 1 < HH / KCH) {
            const unsigned so = (unsigned)((c + 1) & 1) * stageBytes;
            const int k0 = (c + 1) * KCH;
#pragma unroll
            for (int p = 0; p < 2; p++) {
                const int row = p * 64 + lrow;
                cp16(sA0 + so + (unsigned)(row * LDP + lseg) * 4u,
                     g_hsR + (size_t)(m0 + row) * HH + k0 + lseg);
                cp16(sB0 + so + (unsigned)(row * LDP + lseg) * 4u,
                     g_WoutR + (size_t)(n0 + row) * HH + k0 + lseg);
            }
            asm volatile("cp.async.commit_group;" ::: "memory");
            asm volatile("cp.async.wait_group 1;" ::: "memory");
        } else {
            asm volatile("cp.async.wait_group 0;" ::: "memory");
        }
        __syncthreads();

#pragma unroll
        for (int ks = 0; ks < 2; ks++) {
            const int k8 = ks * 8;
            unsigned af[2][4];
#pragma unroll
            for (int mi = 0; mi < 2; mi++) {
                const int base = wm * 32 + mi * 16;
                af[mi][0] = sA[s][(base + gid) * LDP + k8 + tig];
                af[mi][1] = sA[s][(base + gid + 8) * LDP + k8 + tig];
                af[mi][2] = sA[s][(base + gid) * LDP + k8 + tig + 4];
                af[mi][3] = sA[s][(base + gid + 8) * LDP + k8 + tig + 4];
            }
#pragma unroll
            for (int ni = 0; ni < 8; ni++) {
                const int nb = wn * 64 + ni * 8;
                const unsigned b0 = sB[s][(nb + gid) * LDP + k8 + tig];
                const unsigned b1 = sB[s][(nb + gid) * LDP + k8 + tig + 4];
#pragma unroll
                for (int mi = 0; mi < 2; mi++) {
                    mma_tf32(acc[mi][ni],
                             af[mi][0], af[mi][1], af[mi][2], af[mi][3],
                             b0, b1);
                }
            }
        }
        __syncthreads();
    }

    // epilogue: bias + symbolic mask + store
#pragma unroll
    for (int mi = 0; mi < 2; mi++) {
        const int rbase = m0 + wm * 32 + mi * 16;
#pragma unroll
        for (int half = 0; half < 2; half++) {
            const int row = rbase + gid + half * 8;    // bt
            const int t   = row & (SS - 1);
            const bool pz = (t > 0) && (x[row - 1] == 0);
#pragma unroll
            for (int ni = 0; ni < 8; ni++) {
                const int col = n0 + wn * 64 + ni * 8 + tig * 2;
                float v0 = acc[mi][ni][half * 2 + 0] + bout[col];
                float v1 = acc[mi][ni][half * 2 + 1] + bout[col + 1];
                if (pz) {
                    if (col >= 3)     v0 = -INFINITY;
                    if (col + 1 >= 3) v1 = -INFINITY;
                }
                *(float2*)(out + (size_t)row * VV + col) = make_float2(v0, v1);
            }
        }
    }
}

// ---------------- launch ---------------------------------------------------
extern "C" void kernel_launch(void* const* d_in, const int* in_sizes, int n_in,
                              void* d_out, int out_size)
{
    const int*   x     = (const int*)  d_in[0];
    const float* emb   = (const float*)d_in[1];
    const float* W_ih  = (const float*)d_in[2];
    const float* W_hh  = (const float*)d_in[3];
    const float* b_ih  = (const float*)d_in[4];
    const float* b_hh  = (const float*)d_in[5];
    const float* W_out = (const float*)d_in[6];
    const float* b_out = (const float*)d_in[7];
    float* out = (float*)d_out;

    cudaStream_t lo = g_res.lo;

    // main (origin) stream: gather -> inproj -> 4x GRU chunks
    gather_kernel<<<MM, 64>>>(x, emb);

    // fork side stream: W_out rounding runs under gather/inproj
    cudaEventRecord(g_res.ev[0], 0);
    cudaStreamWaitEvent(lo, g_res.ev[0], 0);
    roundw_kernel<<<(VV * HH) / 256, 256, 0, lo>>>(W_out);

    inproj_kernel<<<dim3(MM / 256, 768 / 16), 256>>>(W_ih, b_ih);

    for (int j = 0; j < 4; j++) {
        gru_kernel<<<32, 384>>>(W_hh, b_hh, j * 128);
        cudaEventRecord(g_res.ev[1 + j], 0);
        cudaStreamWaitEvent(lo, g_res.ev[1 + j], 0);
        gemm_out_kernel<<<dim3(VV / 128, BB), 256, 0, lo>>>(b_out, x, out, j);
    }

    // join side stream back into the origin stream
    cudaEventRecord(g_res.ev[5], lo);
    cudaStreamWaitEvent(0, g_res.ev[5], 0);
}

// round 12
// speedup vs baseline: 2.4781x; 1.4075x over previous
#include <cuda_runtime.h>
#include <math.h>

#define BB   4
#define SS   512
#define HH   256
#define VV   32000
#define MM   (BB*SS)     // 2048

// GRU dynamic smem: sxp[128*96] + sh[2*256] + spart[96 float4]
#define SMEM_GRU ((128 * 96 + 2 * 256 + 96 * 4) * 4)

// ---------------- device scratch (no allocation anywhere) ----------------
__device__ float g_embT[HH * MM];            // [k][bt]               2 MB
__device__ float g_xp[(size_t)MM * 768];     // [bt][row]             6 MB
__device__ float g_hsR[(size_t)MM * HH];     // [bt][k] RNA-rounded   2 MB
__device__ float g_WoutR[(size_t)VV * HH];   // [n][k] RNA-rounded   33 MB
__device__ float g_hsave[BB * HH];           // h checkpoint between chunks

// ---------------- kernels fwd-decl for static init ------------------------
__global__ void gru_kernel(const float*, const float*, int);

// ---------------- streams/events (static init: before harness baseline) ---
namespace {
struct OverlapRes {
    cudaStream_t hi, lo;
    cudaEvent_t  ev[8];
    OverlapRes() {
        int least = 0, greatest = 0;
        cudaDeviceGetStreamPriorityRange(&least, &greatest);
        cudaStreamCreateWithPriority(&hi, cudaStreamNonBlocking, greatest);
        cudaStreamCreateWithPriority(&lo, cudaStreamNonBlocking, least);
        for (int i = 0; i < 8; i++)
            cudaEventCreateWithFlags(&ev[i], cudaEventDisableTiming);
        cudaFuncSetAttribute(gru_kernel,
                             cudaFuncAttributeMaxDynamicSharedMemorySize,
                             SMEM_GRU);
    }
};
OverlapRes g_res;
}

// RNA round fp32 -> tf32 bit pattern (round-to-nearest, ties away)
__device__ __forceinline__ float rna_tf32(float v) {
    unsigned b = __float_as_uint(v);
    b = (b + 0x1000u) & 0xFFFFE000u;
    return __uint_as_float(b);
}

// ---------------- kernel A: gather emb -> transposed ----------------------
__global__ void gather_kernel(const int* __restrict__ x,
                              const float* __restrict__ emb)
{
    const int bt  = blockIdx.x;
    const int tid = threadIdx.x;             // 0..63
    const int tok = x[bt];
    const float4 v = *(const float4*)(emb + (size_t)tok * HH + tid * 4);
    const int k = tid * 4;
    g_embT[(k + 0) * MM + bt] = v.x;
    g_embT[(k + 1) * MM + bt] = v.y;
    g_embT[(k + 2) * MM + bt] = v.z;
    g_embT[(k + 3) * MM + bt] = v.w;
}

// ---------------- kernel B: xp = emb @ W_ih^T + b_ih ----------------------
__global__ void __launch_bounds__(256) inproj_kernel(
    const float* __restrict__ W_ih, const float* __restrict__ b_ih)
{
    __shared__ float sW[16 * 256];
    const int r0 = blockIdx.y * 16;
    const int bt = blockIdx.x * 256 + threadIdx.x;
    for (int i = threadIdx.x; i < 16 * 256; i += 256)
        sW[i] = W_ih[(size_t)r0 * 256 + i];
    __syncthreads();

    float acc[16];
#pragma unroll
    for (int ri = 0; ri < 16; ri++) acc[ri] = 0.f;

#pragma unroll 4
    for (int k = 0; k < HH; k++) {
        const float e = g_embT[k * MM + bt];
#pragma unroll
        for (int ri = 0; ri < 16; ri++)
            acc[ri] += e * sW[ri * 256 + k];
    }
    float* o = g_xp + (size_t)bt * 768 + r0;
#pragma unroll
    for (int ri = 0; ri < 16; ri++)
        o[ri] = acc[ri] + b_ih[r0 + ri];
}

// ---------------- kernel B2: RNA-round W_out -------------------------------
__global__ void __launch_bounds__(256) roundw_kernel(const float* __restrict__ Wout)
{
    const size_t i = (size_t)blockIdx.x * 256 + threadIdx.x;
    g_WoutR[i] = rna_tf32(Wout[i]);
}

// ---------------- cp.async helper ------------------------------------------
__device__ __forceinline__ void cp16(unsigned smem_dst, const void* gsrc) {
    asm volatile("cp.async.cg.shared.global [%0], [%1], 16;"
                 :: "r"(smem_dst), "l"(gsrc) : "memory");
}

// ---------------- kernel C: GRU recurrence chunk (128 steps) ---------------
// 4 clusters (1 per batch) x 8 CTAs x 384 threads; CTA owns cols [rank*32,+32).
// Whole chunk's xp slice preloaded into smem -> recurrence loop does NO
// global loads (immune to co-running GEMM's L2 traffic).
__global__ void __launch_bounds__(384, 1) __cluster_dims__(8, 1, 1)
gru_kernel(const float* __restrict__ W_hh, const float* __restrict__ b_hh,
           const int t0)
{
    extern __shared__ float dyn[];
    float*  sxp   = dyn;                         // [128][96]: (s, g*32+c)
    float*  sh    = dyn + 128 * 96;              // [2][256]
    float4* spart = (float4*)(dyn + 128 * 96 + 512);   // [96]

    const int tid  = threadIdx.x;
    const int w    = tid >> 5;       // 0..11
    const int lane = tid & 31;
    const int g    = w >> 2;         // gate 0..2
    const int kc   = w & 3;          // k-chunk 0..3
    unsigned rank;
    asm("mov.u32 %0, %%cluster_ctarank;" : "=r"(rank));
    const int batch = blockIdx.x >> 3;
    const int col   = (int)rank * 32 + lane;

    // preload this chunk's xp slice: 128 steps x 3 gates x 32 cols = 48 KB
    {
        const unsigned sxp_addr = (unsigned)__cvta_generic_to_shared(sxp);
#pragma unroll
        for (int q = 0; q < 8; q++) {
            const int i  = tid + q * 384;        // 0..3071
            const int sg = i >> 3, off = i & 7;
            const int s  = sg / 3, gg = sg - s * 3;
            const float* src = g_xp
                + (size_t)(batch * SS + t0 + s) * 768
                + gg * HH + (int)rank * 32 + off * 4;
            cp16(sxp_addr + (unsigned)(s * 96 + gg * 32 + off * 4) * 4u, src);
        }
        asm volatile("cp.async.commit_group;" ::: "memory");
    }

    // persistent W_hh slice in registers, packed as f32x2 pairs
    unsigned long long wreg[32];
    {
        const ulonglong2* wp =
            (const ulonglong2*)(W_hh + (size_t)(g * HH + col) * HH + kc * 64);
#pragma unroll
        for (int i = 0; i < 16; i++) {
            const ulonglong2 wv = wp[i];
            wreg[2 * i + 0] = wv.x;
            wreg[2 * i + 1] = wv.y;
        }
    }

    float bhr = 0.f, bhz = 0.f, bhn = 0.f;
    int gcol = 0;
    if (tid < 32) {
        gcol = (int)rank * 32 + tid;
        bhr = b_hh[0 * HH + gcol];
        bhz = b_hh[1 * HH + gcol];
        bhn = b_hh[2 * HH + gcol];
    }

    const unsigned sh_addr = (unsigned)__cvta_generic_to_shared(sh);

    // init sh[0] = h(t0): zeros for chunk 0, checkpoint otherwise
    if (tid < HH)
        sh[tid] = (t0 == 0) ? 0.f : g_hsave[batch * HH + tid];
    asm volatile("cp.async.wait_group 0;" ::: "memory");
    __syncthreads();
    asm volatile("barrier.cluster.arrive.aligned;" ::: "memory");

    const int tend = t0 + 128;
    for (int t = t0 + 1; t <= tend; t++) {
        const int cur = (t - 1) & 1;     // t0 multiple of 128 -> buffer 0 first
        const int nxt = t & 1;
        const int s   = t - 1 - t0;

        asm volatile("barrier.cluster.wait.aligned;" ::: "memory");

        // partial dot: packed f32x2, two accumulators
        {
            const float* hb = sh + cur * HH + kc * 64;
            unsigned long long a0 = 0ULL, a1 = 0ULL;
#pragma unroll
            for (int i = 0; i < 64; i += 8) {
                const ulonglong2 h0 = *(const ulonglong2*)(hb + i);
                const ulonglong2 h1 = *(const ulonglong2*)(hb + i + 4);
                asm("fma.rn.f32x2 %0, %1, %2, %0;"
                    : "+l"(a0) : "l"(wreg[i / 2 + 0]), "l"(h0.x));
                asm("fma.rn.f32x2 %0, %1, %2, %0;"
                    : "+l"(a1) : "l"(wreg[i / 2 + 1]), "l"(h0.y));
                asm("fma.rn.f32x2 %0, %1, %2, %0;"
                    : "+l"(a0) : "l"(wreg[i / 2 + 2]), "l"(h1.x));
                asm("fma.rn.f32x2 %0, %1, %2, %0;"
                    : "+l"(a1) : "l"(wreg[i / 2 + 3]), "l"(h1.y));
            }
            const float sv = __uint_as_float((unsigned)(a0 & 0xffffffffu))
                           + __uint_as_float((unsigned)(a0 >> 32))
                           + __uint_as_float((unsigned)(a1 & 0xffffffffu))
                           + __uint_as_float((unsigned)(a1 >> 32));
            ((float*)&spart[g * 32 + lane])[kc] = sv;
        }
        __syncthreads();

        float hnew = 0.f;
        if (tid < 32) {
            const float xr = sxp[s * 96 +  0 + tid];
            const float xz = sxp[s * 96 + 32 + tid];
            const float xn = sxp[s * 96 + 64 + tid];
            const float4 p0 = spart[0 * 32 + tid];
            const float4 p1 = spart[1 * 32 + tid];
            const float4 p2 = spart[2 * 32 + tid];
            const float hr = p0.x + p0.y + p0.z + p0.w + bhr;
            const float hz = p1.x + p1.y + p1.z + p1.w + bhz;
            const float hn = p2.x + p2.y + p2.z + p2.w + bhn;
            const float r  = 1.f / (1.f + __expf(-(xr + hr)));
            const float z  = 1.f / (1.f + __expf(-(xz + hz)));
            const float nv = xn + r * hn;
            const float n  = 1.f - 2.f / (__expf(2.f * nv) + 1.f);   // tanh
            const float ho = sh[cur * HH + gcol];
            hnew = (1.f - z) * n + z * ho;

            const unsigned dst = sh_addr + (unsigned)(nxt * HH + gcol) * 4u;
#pragma unroll
            for (int rk = 0; rk < 8; rk++) {
                unsigned rem;
                asm volatile("mapa.shared::cluster.u32 %0, %1, %2;"
                             : "=r"(rem) : "r"(dst), "r"((unsigned)rk));
                asm volatile("st.shared::cluster.f32 [%0], %1;"
                             :: "r"(rem), "f"(hnew) : "memory");
            }
        }

        // release our DSMEM stores; matching wait at top of next step
        asm volatile("barrier.cluster.arrive.aligned;" ::: "memory");

        // off critical path: GEMM copy (event edge orders it vs GEMM)
        if (tid < 32) {
            g_hsR[(size_t)(batch * SS + t - 1) * HH + gcol] = rna_tf32(hnew);
            if (t == tend)
                g_hsave[batch * HH + gcol] = hnew;    // checkpoint
        }
    }
    asm volatile("barrier.cluster.wait.aligned;" ::: "memory");
}

// ---------------- kernel D: output GEMM chunk (TF32 mma, 128x128) ---------
#define KCH  16          // k-chunk
#define LDP  20          // padded smem row stride (floats)

__device__ __forceinline__ void mma_tf32(float* d, unsigned a0, unsigned a1,
                                         unsigned a2, unsigned a3,
                                         unsigned b0, unsigned b1) {
    asm volatile(
        "mma.sync.aligned.m16n8k8.row.col.f32.tf32.tf32.f32 "
        "{%0,%1,%2,%3}, {%4,%5,%6,%7}, {%8,%9}, {%0,%1,%2,%3};"
        : "+f"(d[0]), "+f"(d[1]), "+f"(d[2]), "+f"(d[3])
        : "r"(a0), "r"(a1), "r"(a2), "r"(a3), "r"(b0), "r"(b1));
}

__global__ void __launch_bounds__(256, 2) gemm_out_kernel(
    const float* __restrict__ bout, const int* __restrict__ x,
    float* __restrict__ out, const int j)
{
    __shared__ unsigned sA[2][128 * LDP];
    __shared__ unsigned sB[2][128 * LDP];

    const int m0   = blockIdx.y * 512 + j * 128;   // rows b*512 + [128j, +128)
    const int n0   = blockIdx.x * 128;
    const int tid  = threadIdx.x;
    const int lane = tid & 31;
    const int wid  = tid >> 5;          // 0..7
    const int wm   = wid & 3;           // 4 warps along m
    const int wn   = wid >> 2;          // 2 warps along n
    const int gid  = lane >> 2;
    const int tig  = lane & 3;

    float acc[2][8][4];
#pragma unroll
    for (int mi = 0; mi < 2; mi++)
#pragma unroll
        for (int ni = 0; ni < 8; ni++)
#pragma unroll
            for (int q = 0; q < 4; q++) acc[mi][ni][q] = 0.f;

    const int lrow = tid >> 2;
    const int lseg = (tid & 3) * 4;
    const unsigned sA0 = (unsigned)__cvta_generic_to_shared(&sA[0][0]);
    const unsigned sB0 = (unsigned)__cvta_generic_to_shared(&sB[0][0]);
    const unsigned stageBytes = 128 * LDP * 4;

    // prefetch chunk 0 into stage 0
#pragma unroll
    for (int p = 0; p < 2; p++) {
        const int row = p * 64 + lrow;
        cp16(sA0 + (unsigned)(row * LDP + lseg) * 4u,
             g_hsR + (size_t)(m0 + row) * HH + lseg);
        cp16(sB0 + (unsigned)(row * LDP + lseg) * 4u,
             g_WoutR + (size_t)(n0 + row) * HH + lseg);
    }
    asm volatile("cp.async.commit_group;" ::: "memory");

    for (int c = 0; c < HH / KCH; c++) {
        const int s = c & 1;
        if (c + 1 < HH / KCH) {
            const unsigned so = (unsigned)((c + 1) & 1) * stageBytes;
            const int k0 = (c + 1) * KCH;
#pragma unroll
            for (int p = 0; p < 2; p++) {
                const int row = p * 64 + lrow;
                cp16(sA0 + so + (unsigned)(row * LDP + lseg) * 4u,
                     g_hsR + (size_t)(m0 + row) * HH + k0 + lseg);
                cp16(sB0 + so + (unsigned)(row * LDP + lseg) * 4u,
                     g_WoutR + (size_t)(n0 + row) * HH + k0 + lseg);
            }
            asm volatile("cp.async.commit_group;" ::: "memory");
            asm volatile("cp.async.wait_group 1;" ::: "memory");
        } else {
            asm volatile("cp.async.wait_group 0;" ::: "memory");
        }
        __syncthreads();

#pragma unroll
        for (int ks = 0; ks < 2; ks++) {
            const int k8 = ks * 8;
            unsigned af[2][4];
#pragma unroll
            for (int mi = 0; mi < 2; mi++) {
                const int base = wm * 32 + mi * 16;
                af[mi][0] = sA[s][(base + gid) * LDP + k8 + tig];
                af[mi][1] = sA[s][(base + gid + 8) * LDP + k8 + tig];
                af[mi][2] = sA[s][(base + gid) * LDP + k8 + tig + 4];
                af[mi][3] = sA[s][(base + gid + 8) * LDP + k8 + tig + 4];
            }
#pragma unroll
            for (int ni = 0; ni < 8; ni++) {
                const int nb = wn * 64 + ni * 8;
                const unsigned b0 = sB[s][(nb + gid) * LDP + k8 + tig];
                const unsigned b1 = sB[s][(nb + gid) * LDP + k8 + tig + 4];
#pragma unroll
                for (int mi = 0; mi < 2; mi++) {
                    mma_tf32(acc[mi][ni],
                             af[mi][0], af[mi][1], af[mi][2], af[mi][3],
                             b0, b1);
                }
            }
        }
        __syncthreads();
    }

    // epilogue: bias + symbolic mask + store
#pragma unroll
    for (int mi = 0; mi < 2; mi++) {
        const int rbase = m0 + wm * 32 + mi * 16;
#pragma unroll
        for (int half = 0; half < 2; half++) {
            const int row = rbase + gid + half * 8;    // bt
            const int t   = row & (SS - 1);
            const bool pz = (t > 0) && (x[row - 1] == 0);
#pragma unroll
            for (int ni = 0; ni < 8; ni++) {
                const int col = n0 + wn * 64 + ni * 8 + tig * 2;
                float v0 = acc[mi][ni][half * 2 + 0] + bout[col];
                float v1 = acc[mi][ni][half * 2 + 1] + bout[col + 1];
                if (pz) {
                    if (col >= 3)     v0 = -INFINITY;
                    if (col + 1 >= 3) v1 = -INFINITY;
                }
                *(float2*)(out + (size_t)row * VV + col) = make_float2(v0, v1);
            }
        }
    }
}

// ---------------- launch ---------------------------------------------------
extern "C" void kernel_launch(void* const* d_in, const int* in_sizes, int n_in,
                              void* d_out, int out_size)
{
    const int*   x     = (const int*)  d_in[0];
    const float* emb   = (const float*)d_in[1];
    const float* W_ih  = (const float*)d_in[2];
    const float* W_hh  = (const float*)d_in[3];
    const float* b_ih  = (const float*)d_in[4];
    const float* b_hh  = (const float*)d_in[5];
    const float* W_out = (const float*)d_in[6];
    const float* b_out = (const float*)d_in[7];
    float* out = (float*)d_out;

    cudaStream_t hi = g_res.hi, lo = g_res.lo;

    // fork both explicit streams from the capture-origin (legacy) stream.
    // NOTHING else runs on the legacy stream -> no implicit-sync edges.
    cudaEventRecord(g_res.ev[0], 0);
    cudaStreamWaitEvent(hi, g_res.ev[0], 0);
    cudaStreamWaitEvent(lo, g_res.ev[0], 0);

    // hi: gather -> inproj -> 4x GRU chunks
    gather_kernel<<<MM, 64, 0, hi>>>(x, emb);
    // lo: W_out rounding (parallel with gather/inproj)
    roundw_kernel<<<(VV * HH) / 256, 256, 0, lo>>>(W_out);

    inproj_kernel<<<dim3(MM / 256, 768 / 16), 256, 0, hi>>>(W_ih, b_ih);

    for (int j = 0; j < 4; j++) {
        gru_kernel<<<32, 384, SMEM_GRU, hi>>>(W_hh, b_hh, j * 128);
        cudaEventRecord(g_res.ev[1 + j], hi);
        cudaStreamWaitEvent(lo, g_res.ev[1 + j], 0);
        gemm_out_kernel<<<dim3(VV / 128, BB), 256, 0, lo>>>(b_out, x, out, j);
    }

    // join both streams back into the origin stream
    cudaEventRecord(g_res.ev[5], hi);
    cudaEventRecord(g_res.ev[6], lo);
    cudaStreamWaitEvent(0, g_res.ev[5], 0);
    cudaStreamWaitEvent(0, g_res.ev[6], 0);
}